// round 16
// baseline (speedup 1.0000x reference)
#include <cuda_runtime.h>
#include <cuda_bf16.h>
#include <cuda_fp16.h>
#include <cstdint>

#define N_NODES 50000
#define N_FEAT  128
#define N_EDGES 800000
#define ALPHA   0.2f
#define EPS     1e-16f

#define N_TILES    391             // ceil(50000/128)
#define SCAN_TILES 49              // ceil(50000/1024)

// ---------------- scratch (device globals; zero-init at load) ---------------
__device__ __half d_Wh16[(size_t)N_NODES * N_FEAT];      // 12.8 MB, gather source
__device__ float d_s1[N_NODES];
__device__ float d_s2[N_NODES];
__device__ int   d_counts[N_NODES];     // invariant: zero on entry to kernel_launch
__device__ int   d_starts[N_NODES + 1];
__device__ int   d_cursor[N_NODES];
__device__ int2  d_ce[N_EDGES];         // {col, float_bits(leakyrelu(e))}, dest-grouped
__device__ unsigned char d_Bhi[32768];  // pre-swizzled bf16 W^T image, hi halves
__device__ unsigned char d_Blo[32768];  // pre-swizzled bf16 W^T image, lo halves
__device__ int   g_is64;

// ---------------- helpers ----------------------------------------------------
__device__ __forceinline__ unsigned swz(unsigned off) {   // SW128 row-local xor
    return off ^ ((off >> 3) & 0x70);
}
__device__ __forceinline__ uint32_t smem_u32(const void* p) {
    uint32_t a;
    asm("{ .reg .u64 t; cvta.to.shared.u64 t, %1; cvt.u32.u64 %0, t; }" : "=r"(a) : "l"(p));
    return a;
}
__device__ __forceinline__ void ldm_x4(uint32_t& r0, uint32_t& r1, uint32_t& r2, uint32_t& r3,
                                       uint32_t addr) {
    asm volatile("ldmatrix.sync.aligned.m8n8.x4.shared.b16 {%0,%1,%2,%3}, [%4];"
                 : "=r"(r0), "=r"(r1), "=r"(r2), "=r"(r3) : "r"(addr));
}
__device__ __forceinline__ void mma_bf16(float* c, uint32_t a0, uint32_t a1, uint32_t a2,
                                         uint32_t a3, uint32_t b0, uint32_t b1) {
    asm volatile(
        "mma.sync.aligned.m16n8k16.row.col.f32.bf16.bf16.f32 "
        "{%0,%1,%2,%3}, {%4,%5,%6,%7}, {%8,%9}, {%0,%1,%2,%3};"
        : "+f"(c[0]), "+f"(c[1]), "+f"(c[2]), "+f"(c[3])
        : "r"(a0), "r"(a1), "r"(a2), "r"(a3), "r"(b0), "r"(b1));
}
__device__ __forceinline__ unsigned short bfb(float x) {
    return __bfloat16_as_ushort(__float2bfloat16(x));
}
__device__ __forceinline__ float bff(unsigned short u) {
    return __bfloat162float(__ushort_as_bfloat16(u));
}
__device__ __forceinline__ int edge_get(const void* ei, int which, int i, int is64) {
    if (is64) return (int)((const long long*)ei)[(size_t)which * N_EDGES + i];
    return ((const int*)ei)[which * N_EDGES + i];
}

// ---------------- prep B + dtype detect + fused degree histogram ------------
__global__ void prep_count_kernel(const float* __restrict__ W, const void* __restrict__ ei) {
    __shared__ int sh_is64;
    const int tid = threadIdx.x;
    if (tid == 0) {
        const unsigned long long* p = (const unsigned long long*)ei;
        int big = 0;
        for (int i = 0; i < 64; i++)
            if (p[i] > (unsigned long long)N_NODES) big++;
        int is64 = (big < 32) ? 1 : 0;
        sh_is64 = is64;
        if (blockIdx.x == 0) g_is64 = is64;
    }
    const int widx = blockIdx.x * 256 + tid;
    if (widx < 16384) {
        const int k = widx >> 7, n = widx & 127;
        float x = W[k * 128 + n];
        unsigned short hi = bfb(x);
        unsigned short lo = bfb(x - bff(hi));
        unsigned off = swz((unsigned)((k >> 6) * 16384 + n * 128 + (k & 63) * 2));
        *(unsigned short*)(d_Bhi + off) = hi;
        *(unsigned short*)(d_Blo + off) = lo;
    }
    __syncthreads();
    const int is64 = sh_is64;
    const int base = blockIdx.x * 2048 + tid * 8;
    if (base + 8 <= N_EDGES) {
        if (is64) {
            const longlong2* p = (const longlong2*)ei;
#pragma unroll
            for (int j = 0; j < 4; j++) {
                longlong2 v = p[(base >> 1) + j];
                atomicAdd(&d_counts[(int)v.x], 1);
                atomicAdd(&d_counts[(int)v.y], 1);
            }
        } else {
            const int4* p = (const int4*)ei;
#pragma unroll
            for (int j = 0; j < 2; j++) {
                int4 v = p[(base >> 2) + j];
                atomicAdd(&d_counts[v.x], 1);
                atomicAdd(&d_counts[v.y], 1);
                atomicAdd(&d_counts[v.z], 1);
                atomicAdd(&d_counts[v.w], 1);
            }
        }
    } else {
        for (int i = base; i < N_EDGES; i++)
            atomicAdd(&d_counts[edge_get(ei, 0, i, is64)], 1);
    }
}

// ---------------- coalesced single-block scan (warp-shuffle) ----------------
__global__ void scan_kernel() {
    __shared__ int warp_off[32];
    __shared__ int tile_sum;
    const int t = threadIdx.x, lane = t & 31, wrp = t >> 5;
    int carry = 0;
    for (int tile = 0; tile < SCAN_TILES; tile++) {
        const int idx = tile * 1024 + t;
        const int v = (idx < N_NODES) ? d_counts[idx] : 0;
        int x = v;
#pragma unroll
        for (int o = 1; o < 32; o <<= 1) {
            int y = __shfl_up_sync(0xffffffffu, x, o);
            if (lane >= o) x += y;
        }
        if (lane == 31) warp_off[wrp] = x;
        __syncthreads();
        if (wrp == 0) {
            int w = warp_off[lane];
            int xw = w;
#pragma unroll
            for (int o = 1; o < 32; o <<= 1) {
                int y = __shfl_up_sync(0xffffffffu, xw, o);
                if (lane >= o) xw += y;
            }
            warp_off[lane] = xw - w;
            if (lane == 31) tile_sum = xw;
        }
        __syncthreads();
        const int s = carry + warp_off[wrp] + x - v;
        if (idx < N_NODES) {
            d_starts[idx] = s;
            d_cursor[idx] = s;
            d_counts[idx] = 0;
        }
        carry += tile_sum;
        __syncthreads();
    }
    if (t == 0) d_starts[N_NODES] = carry;
}

// ---------------- HMMA GEMM: 128x128 tile (R14 config), fused s1/s2 ---------
#define SM_AHI 0
#define SM_ALO 32768
#define SM_BHI 65536
#define SM_BLO 98304
#define SM_TOT 131072

__global__ void __launch_bounds__(256) gemm_mma_kernel(const float* __restrict__ h,
                                                       const float* __restrict__ a_vec) {
    extern __shared__ unsigned char sm[];
    __shared__ float s1s[128], s2s[128];
    const int tid = threadIdx.x;
    const int wid = tid >> 5;
    const int lane = tid & 31;
    const int warpM = wid >> 1, warpN = wid & 1;
    const int m_base = warpM * 32, n_base = warpN * 64;
    const uint32_t sbase = smem_u32(sm);
    const int m0g = blockIdx.x * 128;

#pragma unroll
    for (int i = 0; i < 8; i++) {
        ((uint4*)(sm + SM_BHI))[tid + i * 256] = ((const uint4*)d_Bhi)[tid + i * 256];
        ((uint4*)(sm + SM_BLO))[tid + i * 256] = ((const uint4*)d_Blo)[tid + i * 256];
    }

#pragma unroll
    for (int j = 0; j < 16; j++) {
        const int i = tid + j * 256;
        const int row = i >> 5, q = i & 31;
        const int gr = m0g + row;
        float4 v = make_float4(0.f, 0.f, 0.f, 0.f);
        if (gr < N_NODES) v = ((const float4*)h)[(size_t)gr * 32 + q];
        unsigned short h0 = bfb(v.x), h1 = bfb(v.y), h2 = bfb(v.z), h3 = bfb(v.w);
        unsigned short l0 = bfb(v.x - bff(h0)), l1 = bfb(v.y - bff(h1));
        unsigned short l2 = bfb(v.z - bff(h2)), l3 = bfb(v.w - bff(h3));
        const int k = q * 4;
        unsigned off = swz((unsigned)((k >> 6) * 16384 + row * 128 + (k & 63) * 2));
        *(uint2*)(sm + SM_AHI + off) = make_uint2((unsigned)h0 | ((unsigned)h1 << 16),
                                                  (unsigned)h2 | ((unsigned)h3 << 16));
        *(uint2*)(sm + SM_ALO + off) = make_uint2((unsigned)l0 | ((unsigned)l1 << 16),
                                                  (unsigned)l2 | ((unsigned)l3 << 16));
    }
    __syncthreads();

    float c[2][8][4];
#pragma unroll
    for (int mi = 0; mi < 2; mi++)
#pragma unroll
        for (int ni = 0; ni < 8; ni++)
#pragma unroll
            for (int j = 0; j < 4; j++) c[mi][ni][j] = 0.0f;

    const unsigned arow = (unsigned)(lane & 15);
    const unsigned acol16 = (unsigned)((lane >> 4) * 16);
    const unsigned brow = (unsigned)((lane & 7) + ((lane >> 4) << 3));
    const unsigned bcol16 = (unsigned)(((lane >> 3) & 1) * 16);

#pragma unroll 1
    for (int t3 = 0; t3 < 3; t3++) {
        const uint32_t sA = sbase + ((t3 == 2) ? SM_ALO : SM_AHI);
        const uint32_t sB = sbase + ((t3 == 1) ? SM_BLO : SM_BHI);
#pragma unroll
        for (int kh = 0; kh < 2; kh++) {
#pragma unroll
            for (int ks = 0; ks < 4; ks++) {
                uint32_t a[2][4];
#pragma unroll
                for (int mi = 0; mi < 2; mi++) {
                    unsigned off = (unsigned)(m_base + mi * 16 + arow) * 128 + ks * 32 + acol16;
                    ldm_x4(a[mi][0], a[mi][1], a[mi][2], a[mi][3], sA + kh * 16384 + swz(off));
                }
                uint32_t b[8][2];
#pragma unroll
                for (int ng = 0; ng < 4; ng++) {
                    unsigned off = (unsigned)(n_base + ng * 16 + brow) * 128 + ks * 32 + bcol16;
                    uint32_t r0, r1, r2, r3;
                    ldm_x4(r0, r1, r2, r3, sB + kh * 16384 + swz(off));
                    b[ng * 2][0] = r0; b[ng * 2][1] = r1;
                    b[ng * 2 + 1][0] = r2; b[ng * 2 + 1][1] = r3;
                }
#pragma unroll
                for (int mi = 0; mi < 2; mi++)
#pragma unroll
                    for (int ni = 0; ni < 8; ni++)
                        mma_bf16(c[mi][ni], a[mi][0], a[mi][1], a[mi][2], a[mi][3],
                                 b[ni][0], b[ni][1]);
            }
        }
    }

    const int tig = lane & 3, g = lane >> 2;
    float s1r[4], s2r[4];
#pragma unroll
    for (int mi = 0; mi < 2; mi++) {
#pragma unroll
        for (int half = 0; half < 2; half++) {
            const int lr = m_base + mi * 16 + half * 8 + g;
            const int gr = m0g + lr;
            float s1 = 0.0f, s2 = 0.0f;
#pragma unroll
            for (int ni = 0; ni < 8; ni++) {
                float v0 = c[mi][ni][half * 2 + 0];
                float v1 = c[mi][ni][half * 2 + 1];
                const int col = n_base + ni * 8 + tig * 2;
                s1 += v0 * __ldg(&a_vec[col]) + v1 * __ldg(&a_vec[col + 1]);
                s2 += v0 * __ldg(&a_vec[128 + col]) + v1 * __ldg(&a_vec[128 + col + 1]);
                if (gr < N_NODES)
                    *(__half2*)&d_Wh16[(size_t)gr * 128 + col] = __floats2half2_rn(v0, v1);
            }
            s1 += __shfl_xor_sync(0xffffffffu, s1, 1);
            s1 += __shfl_xor_sync(0xffffffffu, s1, 2);
            s2 += __shfl_xor_sync(0xffffffffu, s2, 1);
            s2 += __shfl_xor_sync(0xffffffffu, s2, 2);
            if (warpN == 0 && tig == 0) { s1s[lr] = s1; s2s[lr] = s2; }
            s1r[mi * 2 + half] = s1;
            s2r[mi * 2 + half] = s2;
        }
    }
    __syncthreads();
    if (warpN == 1 && tig == 0) {
#pragma unroll
        for (int mi = 0; mi < 2; mi++)
#pragma unroll
            for (int half = 0; half < 2; half++) {
                const int lr = m_base + mi * 16 + half * 8 + g;
                const int gr = m0g + lr;
                if (gr < N_NODES) {
                    d_s1[gr] = s1s[lr] + s1r[mi * 2 + half];
                    d_s2[gr] = s2s[lr] + s2r[mi * 2 + half];
                }
            }
    }
}

// ---------------- scatter: leakyrelu(s1+s2) + counting sort, 8 edges/thr ----
__global__ void scatter_kernel(const void* __restrict__ ei) {
    const int t = blockIdx.x * blockDim.x + threadIdx.x;
    const int i = t * 8;
    if (i >= N_EDGES) return;
    int r[8], c[8];
    if (g_is64) {
        const longlong2* p = (const longlong2*)ei;
#pragma unroll
        for (int j = 0; j < 4; j++) {
            longlong2 rr = p[(i >> 1) + j];
            longlong2 cc = p[(N_EDGES >> 1) + (i >> 1) + j];
            r[j * 2] = (int)rr.x; r[j * 2 + 1] = (int)rr.y;
            c[j * 2] = (int)cc.x; c[j * 2 + 1] = (int)cc.y;
        }
    } else {
        const int4* p = (const int4*)ei;
#pragma unroll
        for (int j = 0; j < 2; j++) {
            int4 rr = p[(i >> 2) + j];
            int4 cc = p[(N_EDGES >> 2) + (i >> 2) + j];
            r[j * 4] = rr.x; r[j * 4 + 1] = rr.y; r[j * 4 + 2] = rr.z; r[j * 4 + 3] = rr.w;
            c[j * 4] = cc.x; c[j * 4 + 1] = cc.y; c[j * 4 + 2] = cc.z; c[j * 4 + 3] = cc.w;
        }
    }
#pragma unroll
    for (int j = 0; j < 8; j++) {
        float e = d_s1[r[j]] + d_s2[c[j]];
        e = (e > 0.0f) ? e : ALPHA * e;
        const int p = atomicAdd(&d_cursor[r[j]], 1);
        d_ce[p] = make_int2(c[j], __float_as_int(e));    // one 8B scattered store
    }
}

// ---------------- node: register-cached softmax + shfl-driven gather --------
// deg <= 64 fast path: each lane caches up to 2 {col,e} entries (single
// coalesced d_ce read), computes its softmax weights in registers, and the
// gather loop broadcasts col/w via shfl (26 cyc) instead of an L2 load
// (~300 cyc) -> dependency chain per edge is shfl -> gather load only.
__global__ void node_kernel(float* __restrict__ out) {
    const int warp = (blockIdx.x * blockDim.x + threadIdx.x) >> 5;
    const int lane = threadIdx.x & 31;
    if (warp >= N_NODES) return;
    const int st = d_starts[warp];
    const int en = d_starts[warp + 1];
    const int deg = en - st;
    const uint2* Wv = (const uint2*)d_Wh16;   // one row = 32 uint2 (4 halves each)
    float ax = 0.f, ay = 0.f, az = 0.f, aw = 0.f;

    if (deg <= 64) {
        int2 m0 = make_int2(0, 0), m1 = make_int2(0, 0);
        if (lane < deg)      m0 = d_ce[st + lane];
        if (32 + lane < deg) m1 = d_ce[st + 32 + lane];
        const float e0 = __int_as_float(m0.y);
        const float e1 = __int_as_float(m1.y);

        float rs = ((lane < deg) ? e0 : 0.0f) + ((32 + lane < deg) ? e1 : 0.0f);
#pragma unroll
        for (int off = 16; off > 0; off >>= 1) rs += __shfl_xor_sync(0xffffffffu, rs, off);

        float es = ((lane < deg) ? __expf(e0 - rs) : 0.0f)
                 + ((32 + lane < deg) ? __expf(e1 - rs) : 0.0f);
#pragma unroll
        for (int off = 16; off > 0; off >>= 1) es += __shfl_xor_sync(0xffffffffu, es, off);
        const float inv = 1.0f / (es + EPS);

        // per-lane weights (reference numerics: exp(e - rowsum) / (sum + EPS))
        const float w0l = __expf(e0 - rs) * inv;
        const float w1l = __expf(e1 - rs) * inv;

#pragma unroll 4
        for (int idx = 0; idx < deg; idx++) {
            const int owner = idx & 31;
            const int colv = __shfl_sync(0xffffffffu, (idx < 32) ? m0.x : m1.x, owner);
            const float w  = __shfl_sync(0xffffffffu, (idx < 32) ? w0l : w1l, owner);
            uint2 u = Wv[(size_t)colv * 32 + lane];
            float2 pa = __half22float2(*(__half2*)&u.x);
            float2 pb = __half22float2(*(__half2*)&u.y);
            ax += w * pa.x; ay += w * pa.y; az += w * pb.x; aw += w * pb.y;
        }
    } else {
        // fallback: original 3-pass loop (rare: deg > 64)
        float rs = 0.0f;
        for (int p = st + lane; p < en; p += 32) rs += __int_as_float(d_ce[p].y);
#pragma unroll
        for (int off = 16; off > 0; off >>= 1) rs += __shfl_xor_sync(0xffffffffu, rs, off);
        float es = 0.0f;
        for (int p = st + lane; p < en; p += 32) es += __expf(__int_as_float(d_ce[p].y) - rs);
#pragma unroll
        for (int off = 16; off > 0; off >>= 1) es += __shfl_xor_sync(0xffffffffu, es, off);
        const float inv = 1.0f / (es + EPS);
        for (int p = st; p < en; p++) {
            int2 ce = d_ce[p];
            const float w = __expf(__int_as_float(ce.y) - rs) * inv;
            uint2 u = Wv[(size_t)ce.x * 32 + lane];
            float2 pa = __half22float2(*(__half2*)&u.x);
            float2 pb = __half22float2(*(__half2*)&u.y);
            ax += w * pa.x; ay += w * pa.y; az += w * pb.x; aw += w * pb.y;
        }
    }
    ((float4*)out)[(size_t)warp * 32 + lane] = make_float4(ax, ay, az, aw);
}

// ---------------- launch -----------------------------------------------------
extern "C" void kernel_launch(void* const* d_in, const int* in_sizes, int n_in,
                              void* d_out, int out_size) {
    const float* h = (const float*)d_in[0];
    const void*  ei = d_in[1];
    const float* W = (const float*)d_in[2];
    const float* a = (const float*)d_in[3];
    float* out = (float*)d_out;

    cudaFuncSetAttribute(gemm_mma_kernel, cudaFuncAttributeMaxDynamicSharedMemorySize, SM_TOT);

    prep_count_kernel<<<N_TILES, 256>>>(W, ei);
    scan_kernel<<<1, 1024>>>();
    gemm_mma_kernel<<<N_TILES, 256, SM_TOT>>>(h, a);
    scatter_kernel<<<(N_EDGES / 8 + 255) / 256, 256>>>(ei);
    node_kernel<<<(N_NODES + 7) / 8, 256>>>(out);
    (void)in_sizes; (void)n_in; (void)out_size;
}

// round 17
// speedup vs baseline: 1.3565x; 1.3565x over previous
#include <cuda_runtime.h>
#include <cuda_bf16.h>
#include <cuda_fp16.h>
#include <cstdint>

#define N_NODES 50000
#define N_FEAT  128
#define N_EDGES 800000
#define ALPHA   0.2f
#define EPS     1e-16f

#define N_TILES    391             // gemm tiles: ceil(50000/128)

// ---------------- scratch (device globals; zero-init at load) ---------------
__device__ __half d_Wh16[(size_t)N_NODES * N_FEAT];      // 12.8 MB, gather source
__device__ float d_s1[N_NODES];
__device__ float d_s2[N_NODES];
__device__ int   d_counts[N_NODES];     // invariant: zero on entry to kernel_launch
__device__ int   d_starts[N_NODES + 1];
__device__ int   d_cursor[N_NODES];
__device__ int2  d_ce[N_EDGES];         // {col, float_bits(leakyrelu(e))}, dest-grouped
__device__ unsigned char d_Bhi[32768];  // pre-swizzled bf16 W^T image, hi halves
__device__ unsigned char d_Blo[32768];  // pre-swizzled bf16 W^T image, lo halves
__device__ int   g_is64;

// ---------------- helpers ----------------------------------------------------
__device__ __forceinline__ unsigned swz(unsigned off) {   // SW128 row-local xor
    return off ^ ((off >> 3) & 0x70);
}
__device__ __forceinline__ uint32_t smem_u32(const void* p) {
    uint32_t a;
    asm("{ .reg .u64 t; cvta.to.shared.u64 t, %1; cvt.u32.u64 %0, t; }" : "=r"(a) : "l"(p));
    return a;
}
__device__ __forceinline__ void ldm_x4(uint32_t& r0, uint32_t& r1, uint32_t& r2, uint32_t& r3,
                                       uint32_t addr) {
    asm volatile("ldmatrix.sync.aligned.m8n8.x4.shared.b16 {%0,%1,%2,%3}, [%4];"
                 : "=r"(r0), "=r"(r1), "=r"(r2), "=r"(r3) : "r"(addr));
}
__device__ __forceinline__ void mma_bf16(float* c, uint32_t a0, uint32_t a1, uint32_t a2,
                                         uint32_t a3, uint32_t b0, uint32_t b1) {
    asm volatile(
        "mma.sync.aligned.m16n8k16.row.col.f32.bf16.bf16.f32 "
        "{%0,%1,%2,%3}, {%4,%5,%6,%7}, {%8,%9}, {%0,%1,%2,%3};"
        : "+f"(c[0]), "+f"(c[1]), "+f"(c[2]), "+f"(c[3])
        : "r"(a0), "r"(a1), "r"(a2), "r"(a3), "r"(b0), "r"(b1));
}
__device__ __forceinline__ unsigned short bfb(float x) {
    return __bfloat16_as_ushort(__float2bfloat16(x));
}
__device__ __forceinline__ float bff(unsigned short u) {
    return __bfloat162float(__ushort_as_bfloat16(u));
}
__device__ __forceinline__ int edge_get(const void* ei, int which, int i, int is64) {
    if (is64) return (int)((const long long*)ei)[(size_t)which * N_EDGES + i];
    return ((const int*)ei)[which * N_EDGES + i];
}

// ---------------- prep B + dtype detect + fused degree histogram ------------
__global__ void prep_count_kernel(const float* __restrict__ W, const void* __restrict__ ei) {
    __shared__ int sh_is64;
    const int tid = threadIdx.x;
    if (tid == 0) {
        const unsigned long long* p = (const unsigned long long*)ei;
        int big = 0;
        for (int i = 0; i < 64; i++)
            if (p[i] > (unsigned long long)N_NODES) big++;
        int is64 = (big < 32) ? 1 : 0;
        sh_is64 = is64;
        if (blockIdx.x == 0) g_is64 = is64;
    }
    const int widx = blockIdx.x * 256 + tid;
    if (widx < 16384) {
        const int k = widx >> 7, n = widx & 127;
        float x = W[k * 128 + n];
        unsigned short hi = bfb(x);
        unsigned short lo = bfb(x - bff(hi));
        unsigned off = swz((unsigned)((k >> 6) * 16384 + n * 128 + (k & 63) * 2));
        *(unsigned short*)(d_Bhi + off) = hi;
        *(unsigned short*)(d_Blo + off) = lo;
    }
    __syncthreads();
    const int is64 = sh_is64;
    const int base = blockIdx.x * 2048 + tid * 8;
    if (base + 8 <= N_EDGES) {
        if (is64) {
            const longlong2* p = (const longlong2*)ei;
#pragma unroll
            for (int j = 0; j < 4; j++) {
                longlong2 v = p[(base >> 1) + j];
                atomicAdd(&d_counts[(int)v.x], 1);
                atomicAdd(&d_counts[(int)v.y], 1);
            }
        } else {
            const int4* p = (const int4*)ei;
#pragma unroll
            for (int j = 0; j < 2; j++) {
                int4 v = p[(base >> 2) + j];
                atomicAdd(&d_counts[v.x], 1);
                atomicAdd(&d_counts[v.y], 1);
                atomicAdd(&d_counts[v.z], 1);
                atomicAdd(&d_counts[v.w], 1);
            }
        }
    } else {
        for (int i = base; i < N_EDGES; i++)
            atomicAdd(&d_counts[edge_get(ei, 0, i, is64)], 1);
    }
}

// ---------------- scan as a device function (256 threads, coalesced) --------
// starts = exclusive scan of counts; cursor = starts; counts = 0.
// 25 tiles x 2048 elements, 8 elements/thread, int4-vectorized.
__device__ void device_scan_256() {
    __shared__ int wsum[8];
    __shared__ int s_tile_total;
    const int t = threadIdx.x, lane = t & 31, w = t >> 5;
    int carry = 0;
    for (int tile = 0; tile < 25; tile++) {
        const int base = tile * 2048 + t * 8;
        int v[8];
        const bool fast = (base + 8 <= N_NODES);
        if (fast) {
            int4 a = *(const int4*)&d_counts[base];
            int4 b = *(const int4*)&d_counts[base + 4];
            v[0] = a.x; v[1] = a.y; v[2] = a.z; v[3] = a.w;
            v[4] = b.x; v[5] = b.y; v[6] = b.z; v[7] = b.w;
        } else {
#pragma unroll
            for (int j = 0; j < 8; j++) v[j] = (base + j < N_NODES) ? d_counts[base + j] : 0;
        }
        int tot = 0;
#pragma unroll
        for (int j = 0; j < 8; j++) tot += v[j];
        int x = tot;
#pragma unroll
        for (int o = 1; o < 32; o <<= 1) {
            int y = __shfl_up_sync(0xffffffffu, x, o);
            if (lane >= o) x += y;
        }
        if (lane == 31) wsum[w] = x;
        __syncthreads();
        if (t == 0) {
            int r = 0;
#pragma unroll
            for (int i = 0; i < 8; i++) { int tmp = wsum[i]; wsum[i] = r; r += tmp; }
            s_tile_total = r;
        }
        __syncthreads();
        int run = carry + wsum[w] + x - tot;   // exclusive prefix of this thread
        if (fast) {
            int st[8];
#pragma unroll
            for (int j = 0; j < 8; j++) { st[j] = run; run += v[j]; }
            *(int4*)&d_starts[base]     = make_int4(st[0], st[1], st[2], st[3]);
            *(int4*)&d_starts[base + 4] = make_int4(st[4], st[5], st[6], st[7]);
            *(int4*)&d_cursor[base]     = make_int4(st[0], st[1], st[2], st[3]);
            *(int4*)&d_cursor[base + 4] = make_int4(st[4], st[5], st[6], st[7]);
            *(int4*)&d_counts[base]     = make_int4(0, 0, 0, 0);
            *(int4*)&d_counts[base + 4] = make_int4(0, 0, 0, 0);
        } else {
#pragma unroll
            for (int j = 0; j < 8; j++)
                if (base + j < N_NODES) {
                    d_starts[base + j] = run;
                    d_cursor[base + j] = run;
                    run += v[j];
                    d_counts[base + j] = 0;
                }
        }
        carry += s_tile_total;
        __syncthreads();
    }
    if (t == 0) d_starts[N_NODES] = carry;
}

// ---------------- HMMA GEMM + concurrent scan (block 0) ---------------------
// grid = N_TILES + 1. Block 0 runs the scan (overlapped with GEMM wave 1);
// blocks 1..N_TILES compute 128x128 output tiles with fused s1/s2.
#define SM_AHI 0
#define SM_ALO 32768
#define SM_BHI 65536
#define SM_BLO 98304
#define SM_TOT 131072

__global__ void __launch_bounds__(256) gemm_mma_kernel(const float* __restrict__ h,
                                                       const float* __restrict__ a_vec) {
    if (blockIdx.x == 0) {       // scan block: independent of GEMM data
        device_scan_256();
        return;
    }
    extern __shared__ unsigned char sm[];
    __shared__ float s1s[128], s2s[128];
    const int tid = threadIdx.x;
    const int wid = tid >> 5;
    const int lane = tid & 31;
    const int warpM = wid >> 1, warpN = wid & 1;
    const int m_base = warpM * 32, n_base = warpN * 64;
    const uint32_t sbase = smem_u32(sm);
    const int m0g = (blockIdx.x - 1) * 128;

#pragma unroll
    for (int i = 0; i < 8; i++) {
        ((uint4*)(sm + SM_BHI))[tid + i * 256] = ((const uint4*)d_Bhi)[tid + i * 256];
        ((uint4*)(sm + SM_BLO))[tid + i * 256] = ((const uint4*)d_Blo)[tid + i * 256];
    }

#pragma unroll
    for (int j = 0; j < 16; j++) {
        const int i = tid + j * 256;
        const int row = i >> 5, q = i & 31;
        const int gr = m0g + row;
        float4 v = make_float4(0.f, 0.f, 0.f, 0.f);
        if (gr < N_NODES) v = ((const float4*)h)[(size_t)gr * 32 + q];
        unsigned short h0 = bfb(v.x), h1 = bfb(v.y), h2 = bfb(v.z), h3 = bfb(v.w);
        unsigned short l0 = bfb(v.x - bff(h0)), l1 = bfb(v.y - bff(h1));
        unsigned short l2 = bfb(v.z - bff(h2)), l3 = bfb(v.w - bff(h3));
        const int k = q * 4;
        unsigned off = swz((unsigned)((k >> 6) * 16384 + row * 128 + (k & 63) * 2));
        *(uint2*)(sm + SM_AHI + off) = make_uint2((unsigned)h0 | ((unsigned)h1 << 16),
                                                  (unsigned)h2 | ((unsigned)h3 << 16));
        *(uint2*)(sm + SM_ALO + off) = make_uint2((unsigned)l0 | ((unsigned)l1 << 16),
                                                  (unsigned)l2 | ((unsigned)l3 << 16));
    }
    __syncthreads();

    float c[2][8][4];
#pragma unroll
    for (int mi = 0; mi < 2; mi++)
#pragma unroll
        for (int ni = 0; ni < 8; ni++)
#pragma unroll
            for (int j = 0; j < 4; j++) c[mi][ni][j] = 0.0f;

    const unsigned arow = (unsigned)(lane & 15);
    const unsigned acol16 = (unsigned)((lane >> 4) * 16);
    const unsigned brow = (unsigned)((lane & 7) + ((lane >> 4) << 3));
    const unsigned bcol16 = (unsigned)(((lane >> 3) & 1) * 16);

#pragma unroll 1
    for (int t3 = 0; t3 < 3; t3++) {
        const uint32_t sA = sbase + ((t3 == 2) ? SM_ALO : SM_AHI);
        const uint32_t sB = sbase + ((t3 == 1) ? SM_BLO : SM_BHI);
#pragma unroll
        for (int kh = 0; kh < 2; kh++) {
#pragma unroll
            for (int ks = 0; ks < 4; ks++) {
                uint32_t a[2][4];
#pragma unroll
                for (int mi = 0; mi < 2; mi++) {
                    unsigned off = (unsigned)(m_base + mi * 16 + arow) * 128 + ks * 32 + acol16;
                    ldm_x4(a[mi][0], a[mi][1], a[mi][2], a[mi][3], sA + kh * 16384 + swz(off));
                }
                uint32_t b[8][2];
#pragma unroll
                for (int ng = 0; ng < 4; ng++) {
                    unsigned off = (unsigned)(n_base + ng * 16 + brow) * 128 + ks * 32 + bcol16;
                    uint32_t r0, r1, r2, r3;
                    ldm_x4(r0, r1, r2, r3, sB + kh * 16384 + swz(off));
                    b[ng * 2][0] = r0; b[ng * 2][1] = r1;
                    b[ng * 2 + 1][0] = r2; b[ng * 2 + 1][1] = r3;
                }
#pragma unroll
                for (int mi = 0; mi < 2; mi++)
#pragma unroll
                    for (int ni = 0; ni < 8; ni++)
                        mma_bf16(c[mi][ni], a[mi][0], a[mi][1], a[mi][2], a[mi][3],
                                 b[ni][0], b[ni][1]);
            }
        }
    }

    const int tig = lane & 3, g = lane >> 2;
    float s1r[4], s2r[4];
#pragma unroll
    for (int mi = 0; mi < 2; mi++) {
#pragma unroll
        for (int half = 0; half < 2; half++) {
            const int lr = m_base + mi * 16 + half * 8 + g;
            const int gr = m0g + lr;
            float s1 = 0.0f, s2 = 0.0f;
#pragma unroll
            for (int ni = 0; ni < 8; ni++) {
                float v0 = c[mi][ni][half * 2 + 0];
                float v1 = c[mi][ni][half * 2 + 1];
                const int col = n_base + ni * 8 + tig * 2;
                s1 += v0 * __ldg(&a_vec[col]) + v1 * __ldg(&a_vec[col + 1]);
                s2 += v0 * __ldg(&a_vec[128 + col]) + v1 * __ldg(&a_vec[128 + col + 1]);
                if (gr < N_NODES)
                    *(__half2*)&d_Wh16[(size_t)gr * 128 + col] = __floats2half2_rn(v0, v1);
            }
            s1 += __shfl_xor_sync(0xffffffffu, s1, 1);
            s1 += __shfl_xor_sync(0xffffffffu, s1, 2);
            s2 += __shfl_xor_sync(0xffffffffu, s2, 1);
            s2 += __shfl_xor_sync(0xffffffffu, s2, 2);
            if (warpN == 0 && tig == 0) { s1s[lr] = s1; s2s[lr] = s2; }
            s1r[mi * 2 + half] = s1;
            s2r[mi * 2 + half] = s2;
        }
    }
    __syncthreads();
    if (warpN == 1 && tig == 0) {
#pragma unroll
        for (int mi = 0; mi < 2; mi++)
#pragma unroll
            for (int half = 0; half < 2; half++) {
                const int lr = m_base + mi * 16 + half * 8 + g;
                const int gr = m0g + lr;
                if (gr < N_NODES) {
                    d_s1[gr] = s1s[lr] + s1r[mi * 2 + half];
                    d_s2[gr] = s2s[lr] + s2r[mi * 2 + half];
                }
            }
    }
}

// ---------------- scatter: leakyrelu(s1+s2) + counting sort, 8 edges/thr ----
__global__ void scatter_kernel(const void* __restrict__ ei) {
    const int t = blockIdx.x * blockDim.x + threadIdx.x;
    const int i = t * 8;
    if (i >= N_EDGES) return;
    int r[8], c[8];
    if (g_is64) {
        const longlong2* p = (const longlong2*)ei;
#pragma unroll
        for (int j = 0; j < 4; j++) {
            longlong2 rr = p[(i >> 1) + j];
            longlong2 cc = p[(N_EDGES >> 1) + (i >> 1) + j];
            r[j * 2] = (int)rr.x; r[j * 2 + 1] = (int)rr.y;
            c[j * 2] = (int)cc.x; c[j * 2 + 1] = (int)cc.y;
        }
    } else {
        const int4* p = (const int4*)ei;
#pragma unroll
        for (int j = 0; j < 2; j++) {
            int4 rr = p[(i >> 2) + j];
            int4 cc = p[(N_EDGES >> 2) + (i >> 2) + j];
            r[j * 4] = rr.x; r[j * 4 + 1] = rr.y; r[j * 4 + 2] = rr.z; r[j * 4 + 3] = rr.w;
            c[j * 4] = cc.x; c[j * 4 + 1] = cc.y; c[j * 4 + 2] = cc.z; c[j * 4 + 3] = cc.w;
        }
    }
#pragma unroll
    for (int j = 0; j < 8; j++) {
        float e = d_s1[r[j]] + d_s2[c[j]];
        e = (e > 0.0f) ? e : ALPHA * e;
        const int p = atomicAdd(&d_cursor[r[j]], 1);
        d_ce[p] = make_int2(c[j], __float_as_int(e));    // one 8B scattered store
    }
}

// ---------------- node: rowsum -> expsum -> gather-aggregate (3 passes) -----
// (R14 version: d_ce re-reads are warp-uniform broadcasts -> L1 hits.)
__global__ void node_kernel(float* __restrict__ out) {
    const int warp = (blockIdx.x * blockDim.x + threadIdx.x) >> 5;
    const int lane = threadIdx.x & 31;
    if (warp >= N_NODES) return;
    const int st = d_starts[warp];
    const int en = d_starts[warp + 1];

    float rs = 0.0f;
    for (int p = st + lane; p < en; p += 32) rs += __int_as_float(d_ce[p].y);
#pragma unroll
    for (int off = 16; off > 0; off >>= 1) rs += __shfl_xor_sync(0xffffffffu, rs, off);

    float es = 0.0f;
    for (int p = st + lane; p < en; p += 32) es += __expf(__int_as_float(d_ce[p].y) - rs);
#pragma unroll
    for (int off = 16; off > 0; off >>= 1) es += __shfl_xor_sync(0xffffffffu, es, off);
    const float inv = 1.0f / (es + EPS);

    const uint2* Wv = (const uint2*)d_Wh16;   // one row = 32 uint2 (4 halves each)
    float ax = 0.f, ay = 0.f, az = 0.f, aw = 0.f;
    int p = st;
    for (; p + 4 <= en; p += 4) {
        int2 ce0 = d_ce[p], ce1 = d_ce[p + 1], ce2 = d_ce[p + 2], ce3 = d_ce[p + 3];
        const float w0 = __expf(__int_as_float(ce0.y) - rs) * inv;
        const float w1 = __expf(__int_as_float(ce1.y) - rs) * inv;
        const float w2 = __expf(__int_as_float(ce2.y) - rs) * inv;
        const float w3 = __expf(__int_as_float(ce3.y) - rs) * inv;
        uint2 u0 = Wv[(size_t)ce0.x * 32 + lane];
        uint2 u1 = Wv[(size_t)ce1.x * 32 + lane];
        uint2 u2 = Wv[(size_t)ce2.x * 32 + lane];
        uint2 u3 = Wv[(size_t)ce3.x * 32 + lane];
        float2 p0a = __half22float2(*(__half2*)&u0.x), p0b = __half22float2(*(__half2*)&u0.y);
        float2 p1a = __half22float2(*(__half2*)&u1.x), p1b = __half22float2(*(__half2*)&u1.y);
        float2 p2a = __half22float2(*(__half2*)&u2.x), p2b = __half22float2(*(__half2*)&u2.y);
        float2 p3a = __half22float2(*(__half2*)&u3.x), p3b = __half22float2(*(__half2*)&u3.y);
        ax += w0 * p0a.x + w1 * p1a.x + w2 * p2a.x + w3 * p3a.x;
        ay += w0 * p0a.y + w1 * p1a.y + w2 * p2a.y + w3 * p3a.y;
        az += w0 * p0b.x + w1 * p1b.x + w2 * p2b.x + w3 * p3b.x;
        aw += w0 * p0b.y + w1 * p1b.y + w2 * p2b.y + w3 * p3b.y;
    }
    for (; p < en; p++) {
        int2 ce = d_ce[p];
        const float w = __expf(__int_as_float(ce.y) - rs) * inv;
        uint2 u = Wv[(size_t)ce.x * 32 + lane];
        float2 pa = __half22float2(*(__half2*)&u.x), pb = __half22float2(*(__half2*)&u.y);
        ax += w * pa.x; ay += w * pa.y; az += w * pb.x; aw += w * pb.y;
    }
    ((float4*)out)[(size_t)warp * 32 + lane] = make_float4(ax, ay, az, aw);
}

// ---------------- launch -----------------------------------------------------
extern "C" void kernel_launch(void* const* d_in, const int* in_sizes, int n_in,
                              void* d_out, int out_size) {
    const float* h = (const float*)d_in[0];
    const void*  ei = d_in[1];
    const float* W = (const float*)d_in[2];
    const float* a = (const float*)d_in[3];
    float* out = (float*)d_out;

    cudaFuncSetAttribute(gemm_mma_kernel, cudaFuncAttributeMaxDynamicSharedMemorySize, SM_TOT);

    prep_count_kernel<<<N_TILES, 256>>>(W, ei);
    gemm_mma_kernel<<<N_TILES + 1, 256, SM_TOT>>>(h, a);   // block 0 = scan
    scatter_kernel<<<(N_EDGES / 8 + 255) / 256, 256>>>(ei);
    node_kernel<<<(N_NODES + 7) / 8, 256>>>(out);
    (void)in_sizes; (void)n_in; (void)out_size;
}